// round 8
// baseline (speedup 1.0000x reference)
#include <cuda_runtime.h>
#include <cuda_bf16.h>

#define BB 16
#define FF 32
#define CC 32
#define NN 200
#define TT 48
#define SS 3
#define MC 32               // m-chunk in agg
#define NCH 7               // 6 full chunks + 1 partial (8)
#define NP 224              // padded N
#define NTFLAT (NN * TT)    // 9600

typedef unsigned long long u64;

__device__ __forceinline__ u64 ffma2(u64 a, u64 b, u64 c) {
    u64 d;
    asm("fma.rn.f32x2 %0, %1, %2, %3;" : "=l"(d) : "l"(a), "l"(b), "l"(c));
    return d;
}
__device__ __forceinline__ u64 pack2(float v) {
    u64 d;
    asm("mov.b64 %0, {%1, %1};" : "=l"(d) : "f"(v));
    return d;
}
__device__ __forceinline__ float2 unpack2(u64 v) {
    float2 r;
    asm("mov.b64 {%0, %1}, %2;" : "=f"(r.x), "=f"(r.y) : "l"(v));
    return r;
}

// ---- cp.async helpers ----
__device__ __forceinline__ unsigned smem_u32(const void* p) {
    return (unsigned)__cvta_generic_to_shared(p);
}
#define CPA16(d, s) asm volatile("cp.async.cg.shared.global [%0], [%1], 16;" :: "r"(d), "l"(s))
#define CPC()       asm volatile("cp.async.commit_group;")
#define CPW0()      asm volatile("cp.async.wait_group 0;" ::: "memory")

// Scratch (device globals)
__device__ float g_wh[SS][BB][NTFLAT * CC];       // [(n,t)][c]
__device__ float g_f1t[SS][BB][TT * NP];          // [t][n]
__device__ float g_f2t[SS][BB][TT * NP];          // [t][n]
__device__ float g_f2max[SS][BB][TT];
__device__ unsigned g_adjb[BB * SS][NCH][NP];     // bitmask, word-major
__device__ float g_y[6][BB][NTFLAT * CC];         // slot = 2*s + hop

// ---------------------------------------------------------------------------
// Adjacency bit-pack: grid 48, 256 threads.
// ---------------------------------------------------------------------------
__global__ void adjbit_kernel(const int* __restrict__ support)
{
    const int bs = blockIdx.x;
    const int warp = threadIdx.x >> 5, lane = threadIdx.x & 31;
    const int* adj = support + (size_t)bs * NN * NN;
    for (int pid = warp; pid < NN * NCH; pid += 8) {
        int n = pid / NCH, wi = pid % NCH;
        int mm = wi * 32 + lane;
        int v = (mm < NN) ? (adj[n * NN + mm] > 0) : 0;
        unsigned word = __ballot_sync(0xffffffffu, v);
        if (lane == 0) g_adjb[bs][wi][n] = word;
    }
    if (threadIdx.x < NP - NN) {
        for (int wi = 0; wi < NCH; wi++) g_adjb[bs][wi][NN + threadIdx.x] = 0u;
    }
}

// ---------------------------------------------------------------------------
// Wh + f1/f2 (t-major outputs). grid (75, BB, SS), 256 threads.
// ---------------------------------------------------------------------------
__global__ __launch_bounds__(256) void wh_kernel(
    const float* __restrict__ xin,
    const float* __restrict__ Wb,
    const float* __restrict__ ab,
    int layout)
{
    const int b = blockIdx.y, s = blockIdx.z;
    const int base = blockIdx.x * 128;
    const int tid = threadIdx.x;

    __shared__ float xs[128 * 33];
    __shared__ float Ws[FF * CC];
    __shared__ float as_[2 * CC];

    if (layout == 0) {
        const float* src = xin + (size_t)b * FF * NTFLAT + base;
        #pragma unroll
        for (int k = 0; k < 4; k++) {
            int idx4 = tid + 256 * k;
            int f = idx4 >> 5, r4 = (idx4 & 31) * 4;
            float4 v = *(const float4*)(src + (size_t)f * NTFLAT + r4);
            xs[(r4 + 0) * 33 + f] = v.x;
            xs[(r4 + 1) * 33 + f] = v.y;
            xs[(r4 + 2) * 33 + f] = v.z;
            xs[(r4 + 3) * 33 + f] = v.w;
        }
    } else {
        const float* src = &g_y[2 * s][b][(size_t)base * CC];
        #pragma unroll
        for (int k = 0; k < 4; k++) {
            int idx4 = tid + 256 * k;
            int row = idx4 >> 3, q = (idx4 & 7) * 4;
            float4 v = *(const float4*)(src + idx4 * 4);
            xs[row * 33 + q + 0] = v.x;
            xs[row * 33 + q + 1] = v.y;
            xs[row * 33 + q + 2] = v.z;
            xs[row * 33 + q + 3] = v.w;
        }
    }
    {
        const float* W = Wb + (s * BB + b) * (FF * CC);
        if (tid < 256) ((float4*)Ws)[tid] = ((const float4*)W)[tid];
        if (tid < 2 * CC) as_[tid] = ab[(s * BB + b) * (2 * CC) + tid];
    }
    __syncthreads();

    const int cg = tid & 15, rg = tid >> 4;
    const int r0 = rg * 8;
    float acc[8][2];
    #pragma unroll
    for (int i = 0; i < 8; i++) { acc[i][0] = 0.f; acc[i][1] = 0.f; }

    #pragma unroll 8
    for (int f = 0; f < FF; f++) {
        float2 wv = *(const float2*)&Ws[f * CC + 2 * cg];
        #pragma unroll
        for (int i = 0; i < 8; i++) {
            float xv = xs[(r0 + i) * 33 + f];
            acc[i][0] += xv * wv.x;
            acc[i][1] += xv * wv.y;
        }
    }

    float* whp = &g_wh[s][b][0];
    #pragma unroll
    for (int i = 0; i < 8; i++)
        *(float2*)&whp[(size_t)(base + r0 + i) * CC + 2 * cg] =
            make_float2(acc[i][0], acc[i][1]);

    float a1l = as_[2 * cg], a1h = as_[2 * cg + 1];
    float a2l = as_[CC + 2 * cg], a2h = as_[CC + 2 * cg + 1];
    #pragma unroll
    for (int i = 0; i < 8; i++) {
        float p1 = acc[i][0] * a1l + acc[i][1] * a1h;
        float p2 = acc[i][0] * a2l + acc[i][1] * a2h;
        #pragma unroll
        for (int off = 8; off >= 1; off >>= 1) {
            p1 += __shfl_xor_sync(0xffffffffu, p1, off);
            p2 += __shfl_xor_sync(0xffffffffu, p2, off);
        }
        if (cg == 0) {
            int row = base + r0 + i;
            int n = row / TT, t = row % TT;
            g_f1t[s][b][t * NP + n] = p1;
            g_f2t[s][b][t * NP + n] = p2;
        }
    }
}

// ---------------------------------------------------------------------------
__global__ void f2max_kernel()
{
    const int b = blockIdx.x, s = blockIdx.y, t = threadIdx.x;
    if (t < TT) {
        const float* p = &g_f2t[s][b][t * NP];
        float m = -1e30f;
        for (int n = 0; n < NN; n++) m = fmaxf(m, p[n]);
        g_f2max[s][b][t] = m;
    }
}

// ---------------------------------------------------------------------------
// Attention-aggregation, t-major, FFMA2 n-paired.
// grid (TT, BB, SS), block 256. c = tid&31, ng = tid>>5; thread owns
// n in [28*ng, 28*ng+28) as 14 packed-pair accumulators.
// ---------------------------------------------------------------------------
__global__ __launch_bounds__(256) void agg_kernel(int hop)
{
    const int t = blockIdx.x, b = blockIdx.y, s = blockIdx.z;
    const int bs = b * SS + s;
    const int tid = threadIdx.x;

    __shared__ __align__(16) float whs[2][MC * 36];   // [m][c] stride 36
    __shared__ __align__(16) float wsm[MC * NP];      // [m][n]  28672 B
    __shared__ __align__(16) float f2c[2][MC];
    __shared__ __align__(16) unsigned adjw[2][NP];
    __shared__ float zsm[NN];

    const float* whbase = &g_wh[s][b][0];
    const float* f1tp = &g_f1t[s][b][t * NP];
    const float* f2tp = &g_f2t[s][b][t * NP];
    const float fms = g_f2max[s][b][t];

    auto prefetch = [&](int k, int bf) {
        const int m0 = k * MC;
        {
            int m = tid >> 3, q = tid & 7;
            int mrow = min(m0 + m, NN - 1);
            CPA16(smem_u32(&whs[bf][m * 36 + q * 4]),
                  whbase + ((size_t)mrow * TT + t) * CC + q * 4);
        }
        if (tid < MC / 4)
            CPA16(smem_u32(&f2c[bf][tid * 4]), f2tp + m0 + tid * 4);
        if (tid < NP / 4)
            CPA16(smem_u32(&adjw[bf][tid * 4]), &g_adjb[bs][k][tid * 4]);
        CPC();
    };

    prefetch(0, 0);

    // zero wsm pad columns n in [NN, NP) once (stay zero: step1 writes n<NN only)
    for (int idx = tid; idx < MC * (NP - NN); idx += 256) {
        int m = idx / (NP - NN), n = NN + idx % (NP - NN);
        wsm[m * NP + n] = 0.f;
    }

    float f1v = 0.f, mhv = 0.f, z = 0.f;
    if (tid < NN) {
        f1v = f1tp[tid];
        float sv = f1v + fms;
        mhv = fmaxf(sv, 0.2f * sv);
    }

    const int c = tid & 31, ng = tid >> 5;
    const int nbase = 28 * ng;
    u64 acc[14];
    #pragma unroll
    for (int p = 0; p < 14; p++) acc[p] = 0ull;

    for (int k = 0; k < NCH; k++) {
        const int bf = k & 1;
        const int mc = (k == NCH - 1) ? (NN - (NCH - 1) * MC) : MC;   // 8 or 32
        CPW0();
        __syncthreads();
        if (k + 1 < NCH) prefetch(k + 1, bf ^ 1);

        // step 1: thread n = tid computes w for all m in chunk -> wsm[m][n]
        if (tid < NN) {
            unsigned aw = adjw[bf][tid];
            #pragma unroll 8
            for (int m = 0; m < mc; m++) {
                float sv = f1v + f2c[bf][m];
                float e = fmaxf(sv, 0.2f * sv);
                float w = ((aw >> m) & 1u) ? __expf(e - mhv) : 0.f;
                wsm[m * NP + tid] = w;
                z += w;
            }
        }
        __syncthreads();

        // step 2: acc[p] += (w[n2p], w[n2p+1]) * (wh, wh)
        #pragma unroll 4
        for (int m = 0; m < mc; m++) {
            u64 whp = pack2(whs[bf][m * 36 + c]);
            const longlong2* wp = (const longlong2*)&wsm[m * NP + nbase];
            #pragma unroll
            for (int q = 0; q < 7; q++) {
                longlong2 v = wp[q];
                acc[2 * q]     = ffma2((u64)v.x, whp, acc[2 * q]);
                acc[2 * q + 1] = ffma2((u64)v.y, whp, acc[2 * q + 1]);
            }
        }
    }

    if (tid < NN) zsm[tid] = z;
    __syncthreads();

    const int slot = 2 * s + hop;
    float* yp = &g_y[slot][b][0];
    #pragma unroll
    for (int p = 0; p < 14; p++) {
        int n0p = nbase + 2 * p;
        if (n0p >= NN) break;
        float2 hv = unpack2(acc[p]);
        float z0 = fmaxf(zsm[n0p], 1e-30f);
        float h0 = __fdividef(hv.x, z0);
        float y0;
        if (hop == 0) y0 = (h0 > 0.f) ? h0 : (__expf(h0) - 1.f);
        else          y0 = fmaxf(h0, 0.f);
        yp[(size_t)(n0p * TT + t) * CC + c] = y0;
        if (n0p + 1 < NN) {
            float z1 = fmaxf(zsm[n0p + 1], 1e-30f);
            float h1 = __fdividef(hv.y, z1);
            float y1;
            if (hop == 0) y1 = (h1 > 0.f) ? h1 : (__expf(h1) - 1.f);
            else          y1 = fmaxf(h1, 0.f);
            yp[(size_t)((n0p + 1) * TT + t) * CC + c] = y1;
        }
    }
}

// ---------------------------------------------------------------------------
// Final concat + 1x1 conv. grid (NN, BB), block 192.
// ---------------------------------------------------------------------------
__global__ __launch_bounds__(192) void mlp_kernel(
    const float* __restrict__ x,
    const float* __restrict__ mw,
    const float* __restrict__ mb,
    float* __restrict__ out)
{
    const int n = blockIdx.x, b = blockIdx.y;
    const int tid = threadIdx.x;
    __shared__ float hb[TT * 32];
    __shared__ float wb[64 * 36];

    const int og = tid % 16, tg = tid / 16;
    float acc[4][4];
    #pragma unroll
    for (int i = 0; i < 4; i++)
        #pragma unroll
        for (int j = 0; j < 4; j++) acc[i][j] = 0.f;

    for (int blk = 0; blk < 7; blk++) {
        __syncthreads();
        if (blk == 0) {
            for (int idx = tid; idx < TT * 32; idx += 192) {
                int f = idx / TT, t = idx % TT;
                hb[t * 32 + f] = x[((size_t)(b * FF + f) * NN + n) * TT + t];
            }
        } else {
            const float* src = &g_y[blk - 1][b][(size_t)n * TT * CC];
            for (int idx = tid; idx < TT * 32; idx += 192) hb[idx] = src[idx];
        }
        for (int idx = tid; idx < 64 * 32; idx += 192) {
            int o = idx / 32, c = idx % 32;
            wb[o * 36 + c] = mw[o * 224 + blk * 32 + c];
        }
        __syncthreads();

        #pragma unroll
        for (int cc = 0; cc < 32; cc += 4) {
            float4 hv[4], wv[4];
            #pragma unroll
            for (int j = 0; j < 4; j++) hv[j] = *(const float4*)&hb[(tg * 4 + j) * 32 + cc];
            #pragma unroll
            for (int i = 0; i < 4; i++) wv[i] = *(const float4*)&wb[(og + 16 * i) * 36 + cc];
            #pragma unroll
            for (int i = 0; i < 4; i++)
                #pragma unroll
                for (int j = 0; j < 4; j++)
                    acc[i][j] += wv[i].x * hv[j].x + wv[i].y * hv[j].y
                               + wv[i].z * hv[j].z + wv[i].w * hv[j].w;
        }
    }

    #pragma unroll
    for (int i = 0; i < 4; i++) {
        int o = og + 16 * i;
        float bias = mb[o];
        float4 r = make_float4(acc[i][0] + bias, acc[i][1] + bias,
                               acc[i][2] + bias, acc[i][3] + bias);
        *(float4*)&out[((size_t)(b * 64 + o) * NN + n) * TT + tg * 4] = r;
    }
}

// ---------------------------------------------------------------------------
extern "C" void kernel_launch(void* const* d_in, const int* in_sizes, int n_in,
                              void* d_out, int out_size)
{
    const float* x       = (const float*)d_in[0];
    const int*   support = (const int*)  d_in[1];
    const float* W1      = (const float*)d_in[2];
    const float* a1      = (const float*)d_in[3];
    const float* WK      = (const float*)d_in[4];
    const float* aK      = (const float*)d_in[5];
    const float* mw      = (const float*)d_in[6];
    const float* mb      = (const float*)d_in[7];
    float* out = (float*)d_out;

    dim3 gwh(NTFLAT / 128, BB, SS);
    dim3 gfm(BB, SS);
    dim3 gagg(TT, BB, SS);
    dim3 gmlp(NN, BB);

    adjbit_kernel<<<BB * SS, 256>>>(support);

    wh_kernel<<<gwh, 256>>>(x, W1, a1, 0);
    f2max_kernel<<<gfm, 64>>>();
    agg_kernel<<<gagg, 256>>>(0);

    wh_kernel<<<gwh, 256>>>(x, WK, aK, 1);
    f2max_kernel<<<gfm, 64>>>();
    agg_kernel<<<gagg, 256>>>(1);

    mlp_kernel<<<gmlp, 192>>>(x, mw, mb, out);
}

// round 9
// speedup vs baseline: 1.0087x; 1.0087x over previous
#include <cuda_runtime.h>
#include <cuda_bf16.h>

#define BB 16
#define FF 32
#define CC 32
#define NN 200
#define TT 48
#define SS 3
#define MC 24               // m-chunk in agg (3 k-steps of 8)
#define NCH 9               // 8 full chunks + 1 partial (8)
#define NP 224              // padded N (14 x 16-row mma bands)
#define NTFLAT (NN * TT)    // 9600

// ---- tf32 helpers ----
__device__ __forceinline__ unsigned tf32r(float f) {
    unsigned u; asm("cvt.rna.tf32.f32 %0, %1;" : "=r"(u) : "f"(f)); return u;
}
__device__ __forceinline__ void mma_tf32(float* d,
    unsigned a0, unsigned a1, unsigned a2, unsigned a3,
    unsigned b0, unsigned b1)
{
    asm("mma.sync.aligned.m16n8k8.row.col.f32.tf32.tf32.f32 "
        "{%0,%1,%2,%3}, {%4,%5,%6,%7}, {%8,%9}, {%0,%1,%2,%3};"
        : "+f"(d[0]), "+f"(d[1]), "+f"(d[2]), "+f"(d[3])
        : "r"(a0), "r"(a1), "r"(a2), "r"(a3), "r"(b0), "r"(b1));
}

// ---- cp.async helpers ----
__device__ __forceinline__ unsigned smem_u32(const void* p) {
    return (unsigned)__cvta_generic_to_shared(p);
}
#define CPA16(d, s) asm volatile("cp.async.cg.shared.global [%0], [%1], 16;" :: "r"(d), "l"(s))
#define CPC()       asm volatile("cp.async.commit_group;")
#define CPW0()      asm volatile("cp.async.wait_group 0;" ::: "memory")

// Scratch (device globals)
__device__ float g_whhi[SS][BB][NTFLAT * CC];     // tf32 hi part of Wh, [(n,t)][c]
__device__ float g_whlo[SS][BB][NTFLAT * CC];     // tf32 lo part
__device__ float g_f1t[SS][BB][TT * NP];          // [t][n]
__device__ float g_f2t[SS][BB][TT * NP];          // [t][n]
__device__ float g_f2max[SS][BB][TT];
__device__ unsigned g_adjb[BB * SS][NCH][NP];     // 24-bit masks per chunk
__device__ float g_y[6][BB][NTFLAT * CC];         // slot = 2*s + hop

// ---------------------------------------------------------------------------
// Adjacency bit-pack (24 bits per chunk word). grid 48, 256 threads.
// ---------------------------------------------------------------------------
__global__ void adjbit_kernel(const int* __restrict__ support)
{
    const int bs = blockIdx.x;
    const int warp = threadIdx.x >> 5, lane = threadIdx.x & 31;
    const int* adj = support + (size_t)bs * NN * NN;
    for (int pid = warp; pid < NN * NCH; pid += 8) {
        int n = pid / NCH, wi = pid % NCH;
        int mm = wi * MC + lane;
        int v = (lane < MC && mm < NN) ? (adj[n * NN + mm] > 0) : 0;
        unsigned word = __ballot_sync(0xffffffffu, v);
        if (lane == 0) g_adjb[bs][wi][n] = word;
    }
    if (threadIdx.x < NP - NN) {
        for (int wi = 0; wi < NCH; wi++) g_adjb[bs][wi][NN + threadIdx.x] = 0u;
    }
}

// ---------------------------------------------------------------------------
// Wh + f1/f2 (t-major f-outputs, tf32-split Wh). grid (75, BB, SS), 256 thr.
// ---------------------------------------------------------------------------
__global__ __launch_bounds__(256) void wh_kernel(
    const float* __restrict__ xin,
    const float* __restrict__ Wb,
    const float* __restrict__ ab,
    int layout)
{
    const int b = blockIdx.y, s = blockIdx.z;
    const int base = blockIdx.x * 128;
    const int tid = threadIdx.x;

    __shared__ float xs[128 * 33];
    __shared__ float Ws[FF * CC];
    __shared__ float as_[2 * CC];

    if (layout == 0) {
        const float* src = xin + (size_t)b * FF * NTFLAT + base;
        #pragma unroll
        for (int k = 0; k < 4; k++) {
            int idx4 = tid + 256 * k;
            int f = idx4 >> 5, r4 = (idx4 & 31) * 4;
            float4 v = *(const float4*)(src + (size_t)f * NTFLAT + r4);
            xs[(r4 + 0) * 33 + f] = v.x;
            xs[(r4 + 1) * 33 + f] = v.y;
            xs[(r4 + 2) * 33 + f] = v.z;
            xs[(r4 + 3) * 33 + f] = v.w;
        }
    } else {
        const float* src = &g_y[2 * s][b][(size_t)base * CC];
        #pragma unroll
        for (int k = 0; k < 4; k++) {
            int idx4 = tid + 256 * k;
            int row = idx4 >> 3, q = (idx4 & 7) * 4;
            float4 v = *(const float4*)(src + idx4 * 4);
            xs[row * 33 + q + 0] = v.x;
            xs[row * 33 + q + 1] = v.y;
            xs[row * 33 + q + 2] = v.z;
            xs[row * 33 + q + 3] = v.w;
        }
    }
    {
        const float* W = Wb + (s * BB + b) * (FF * CC);
        if (tid < 256) ((float4*)Ws)[tid] = ((const float4*)W)[tid];
        if (tid < 2 * CC) as_[tid] = ab[(s * BB + b) * (2 * CC) + tid];
    }
    __syncthreads();

    const int cg = tid & 15, rg = tid >> 4;
    const int r0 = rg * 8;
    float acc[8][2];
    #pragma unroll
    for (int i = 0; i < 8; i++) { acc[i][0] = 0.f; acc[i][1] = 0.f; }

    #pragma unroll 8
    for (int f = 0; f < FF; f++) {
        float2 wv = *(const float2*)&Ws[f * CC + 2 * cg];
        #pragma unroll
        for (int i = 0; i < 8; i++) {
            float xv = xs[(r0 + i) * 33 + f];
            acc[i][0] += xv * wv.x;
            acc[i][1] += xv * wv.y;
        }
    }

    float* hp = &g_whhi[s][b][0];
    float* lp = &g_whlo[s][b][0];
    #pragma unroll
    for (int i = 0; i < 8; i++) {
        unsigned h0 = tf32r(acc[i][0]);
        unsigned h1 = tf32r(acc[i][1]);
        float l0 = acc[i][0] - __uint_as_float(h0);
        float l1 = acc[i][1] - __uint_as_float(h1);
        size_t off = (size_t)(base + r0 + i) * CC + 2 * cg;
        *(float2*)&hp[off] = make_float2(__uint_as_float(h0), __uint_as_float(h1));
        *(float2*)&lp[off] = make_float2(__uint_as_float(tf32r(l0)),
                                         __uint_as_float(tf32r(l1)));
    }

    float a1l = as_[2 * cg], a1h = as_[2 * cg + 1];
    float a2l = as_[CC + 2 * cg], a2h = as_[CC + 2 * cg + 1];
    #pragma unroll
    for (int i = 0; i < 8; i++) {
        float p1 = acc[i][0] * a1l + acc[i][1] * a1h;
        float p2 = acc[i][0] * a2l + acc[i][1] * a2h;
        #pragma unroll
        for (int off = 8; off >= 1; off >>= 1) {
            p1 += __shfl_xor_sync(0xffffffffu, p1, off);
            p2 += __shfl_xor_sync(0xffffffffu, p2, off);
        }
        if (cg == 0) {
            int row = base + r0 + i;
            int n = row / TT, t = row % TT;
            g_f1t[s][b][t * NP + n] = p1;
            g_f2t[s][b][t * NP + n] = p2;
        }
    }
}

// ---------------------------------------------------------------------------
__global__ void f2max_kernel()
{
    const int b = blockIdx.x, s = blockIdx.y, t = threadIdx.x;
    if (t < TT) {
        const float* p = &g_f2t[s][b][t * NP];
        float m = -1e30f;
        for (int n = 0; n < NN; n++) m = fmaxf(m, p[n]);
        g_f2max[s][b][t] = m;
    }
}

// ---------------------------------------------------------------------------
// Attention-aggregation, tf32 3x mma. grid (TT, BB, SS), block 448 (14 warps).
// Warp w owns n-rows [16w, 16w+16); 4 c-tiles of 8 per warp.
// ---------------------------------------------------------------------------
__global__ __launch_bounds__(448, 2) void agg_kernel(int hop)
{
    const int t = blockIdx.x, b = blockIdx.y, s = blockIdx.z;
    const int bs = b * SS + s;
    const int tid = threadIdx.x;
    const int lane = tid & 31, wid = tid >> 5;
    const int grp = lane >> 2, kq = lane & 3;

    __shared__ __align__(16) float whhi_s[2][MC * 36];   // [m][c] stride 36
    __shared__ __align__(16) float whlo_s[2][MC * 36];
    __shared__ __align__(16) float wsm[NP * 28];         // [n][m] stride 28
    __shared__ __align__(16) float f2c[2][MC];
    __shared__ __align__(16) unsigned adjw[2][NP];
    __shared__ float zsm[NP];

    const float* whhib = &g_whhi[s][b][0];
    const float* whlob = &g_whlo[s][b][0];
    const float* f1tp = &g_f1t[s][b][t * NP];
    const float* f2tp = &g_f2t[s][b][t * NP];
    const float fms = g_f2max[s][b][t];

    auto prefetch = [&](int k, int bf) {
        const int m0 = k * MC;
        if (tid < 2 * MC * 8) {                 // 384 threads: hi then lo
            int i = tid;
            const float* srcb = whhib;
            float* dstb = &whhi_s[bf][0];
            if (i >= MC * 8) { i -= MC * 8; srcb = whlob; dstb = &whlo_s[bf][0]; }
            int m = i >> 3, q = i & 7;
            int mrow = min(m0 + m, NN - 1);
            CPA16(smem_u32(&dstb[m * 36 + q * 4]),
                  srcb + ((size_t)mrow * TT + t) * CC + q * 4);
        }
        if (tid < MC / 4)
            CPA16(smem_u32(&f2c[bf][tid * 4]), f2tp + m0 + tid * 4);
        if (tid < NP / 4)
            CPA16(smem_u32(&adjw[bf][tid * 4]), &g_adjb[bs][k][tid * 4]);
        CPC();
    };

    prefetch(0, 0);

    // zero wsm pad rows [NN, NP) once
    for (int i = tid; i < (NP - NN) * 28; i += 448)
        wsm[(NN + i / 28) * 28 + (i % 28)] = 0.f;

    float f1v = 0.f, mhv = 0.f, z = 0.f;
    if (tid < NN) {
        f1v = f1tp[tid];
        float sv = f1v + fms;
        mhv = fmaxf(sv, 0.2f * sv);
    }

    float d[4][4];
    #pragma unroll
    for (int j = 0; j < 4; j++)
        #pragma unroll
        for (int q = 0; q < 4; q++) d[j][q] = 0.f;

    const int r0 = 16 * wid + grp;

    for (int k = 0; k < NCH; k++) {
        const int bf = k & 1;
        const int mc = (k == NCH - 1) ? (NN - (NCH - 1) * MC) : MC;   // 8 or 24
        CPW0();
        __syncthreads();
        if (k + 1 < NCH) prefetch(k + 1, bf ^ 1);

        // step 1: thread n computes weights -> wsm[n][m], accumulates Z
        if (tid < NN) {
            unsigned aw = adjw[bf][tid];
            #pragma unroll
            for (int q = 0; q < MC / 4; q++) {
                if (4 * q >= mc) break;
                float4 wq;
                float* wp = &wq.x;
                #pragma unroll
                for (int j = 0; j < 4; j++) {
                    int m = 4 * q + j;
                    float sv = f1v + f2c[bf][m];
                    float e = fmaxf(sv, 0.2f * sv);
                    float w = ((aw >> m) & 1u) ? __expf(e - mhv) : 0.f;
                    wp[j] = w;
                    z += w;
                }
                *(float4*)&wsm[tid * 28 + 4 * q] = wq;
            }
        }
        __syncthreads();

        // step 2: tf32 3x mma over k-steps of 8
        const int nks = mc >> 3;
        for (int ks = 0; ks < nks; ks++) {
            float af0 = wsm[r0 * 28 + ks * 8 + kq];
            float af1 = wsm[(r0 + 8) * 28 + ks * 8 + kq];
            float af2 = wsm[r0 * 28 + ks * 8 + kq + 4];
            float af3 = wsm[(r0 + 8) * 28 + ks * 8 + kq + 4];
            unsigned ah0 = tf32r(af0), ah1 = tf32r(af1);
            unsigned ah2 = tf32r(af2), ah3 = tf32r(af3);
            unsigned al0 = tf32r(af0 - __uint_as_float(ah0));
            unsigned al1 = tf32r(af1 - __uint_as_float(ah1));
            unsigned al2 = tf32r(af2 - __uint_as_float(ah2));
            unsigned al3 = tf32r(af3 - __uint_as_float(ah3));
            #pragma unroll
            for (int j = 0; j < 4; j++) {
                int c0 = 8 * j + grp;
                int mr = ks * 8 + kq;
                unsigned bh0 = __float_as_uint(whhi_s[bf][mr * 36 + c0]);
                unsigned bh1 = __float_as_uint(whhi_s[bf][(mr + 4) * 36 + c0]);
                unsigned bl0 = __float_as_uint(whlo_s[bf][mr * 36 + c0]);
                unsigned bl1 = __float_as_uint(whlo_s[bf][(mr + 4) * 36 + c0]);
                mma_tf32(d[j], ah0, ah1, ah2, ah3, bh0, bh1);
                mma_tf32(d[j], al0, al1, al2, al3, bh0, bh1);
                mma_tf32(d[j], ah0, ah1, ah2, ah3, bl0, bl1);
            }
        }
    }

    if (tid < NN) zsm[tid] = z;
    __syncthreads();

    const int slot = 2 * s + hop;
    float* yp = &g_y[slot][b][0];
    #pragma unroll
    for (int half = 0; half < 2; half++) {
        int n = r0 + 8 * half;
        if (n < NN) {
            float zv = fmaxf(zsm[n], 1e-30f);
            #pragma unroll
            for (int j = 0; j < 4; j++) {
                float h0 = __fdividef(d[j][2 * half], zv);
                float h1 = __fdividef(d[j][2 * half + 1], zv);
                float y0, y1;
                if (hop == 0) {
                    y0 = (h0 > 0.f) ? h0 : (__expf(h0) - 1.f);
                    y1 = (h1 > 0.f) ? h1 : (__expf(h1) - 1.f);
                } else {
                    y0 = fmaxf(h0, 0.f);
                    y1 = fmaxf(h1, 0.f);
                }
                *(float2*)&yp[(size_t)(n * TT + t) * CC + 8 * j + 2 * kq] =
                    make_float2(y0, y1);
            }
        }
    }
}

// ---------------------------------------------------------------------------
// Final concat + 1x1 conv. grid (NN, BB), block 192.
// ---------------------------------------------------------------------------
__global__ __launch_bounds__(192) void mlp_kernel(
    const float* __restrict__ x,
    const float* __restrict__ mw,
    const float* __restrict__ mb,
    float* __restrict__ out)
{
    const int n = blockIdx.x, b = blockIdx.y;
    const int tid = threadIdx.x;
    __shared__ float hb[TT * 32];
    __shared__ float wb[64 * 36];

    const int og = tid % 16, tg = tid / 16;
    float acc[4][4];
    #pragma unroll
    for (int i = 0; i < 4; i++)
        #pragma unroll
        for (int j = 0; j < 4; j++) acc[i][j] = 0.f;

    for (int blk = 0; blk < 7; blk++) {
        __syncthreads();
        if (blk == 0) {
            for (int idx = tid; idx < TT * 32; idx += 192) {
                int f = idx / TT, t = idx % TT;
                hb[t * 32 + f] = x[((size_t)(b * FF + f) * NN + n) * TT + t];
            }
        } else {
            const float* src = &g_y[blk - 1][b][(size_t)n * TT * CC];
            for (int idx = tid; idx < TT * 32; idx += 192) hb[idx] = src[idx];
        }
        for (int idx = tid; idx < 64 * 32; idx += 192) {
            int o = idx / 32, c = idx % 32;
            wb[o * 36 + c] = mw[o * 224 + blk * 32 + c];
        }
        __syncthreads();

        #pragma unroll
        for (int cc = 0; cc < 32; cc += 4) {
            float4 hv[4], wv[4];
            #pragma unroll
            for (int j = 0; j < 4; j++) hv[j] = *(const float4*)&hb[(tg * 4 + j) * 32 + cc];
            #pragma unroll
            for (int i = 0; i < 4; i++) wv[i] = *(const float4*)&wb[(og + 16 * i) * 36 + cc];
            #pragma unroll
            for (int i = 0; i < 4; i++)
                #pragma unroll
                for (int j = 0; j < 4; j++)
                    acc[i][j] += wv[i].x * hv[j].x + wv[i].y * hv[j].y
                               + wv[i].z * hv[j].z + wv[i].w * hv[j].w;
        }
    }

    #pragma unroll
    for (int i = 0; i < 4; i++) {
        int o = og + 16 * i;
        float bias = mb[o];
        float4 r = make_float4(acc[i][0] + bias, acc[i][1] + bias,
                               acc[i][2] + bias, acc[i][3] + bias);
        *(float4*)&out[((size_t)(b * 64 + o) * NN + n) * TT + tg * 4] = r;
    }
}

// ---------------------------------------------------------------------------
extern "C" void kernel_launch(void* const* d_in, const int* in_sizes, int n_in,
                              void* d_out, int out_size)
{
    const float* x       = (const float*)d_in[0];
    const int*   support = (const int*)  d_in[1];
    const float* W1      = (const float*)d_in[2];
    const float* a1      = (const float*)d_in[3];
    const float* WK      = (const float*)d_in[4];
    const float* aK      = (const float*)d_in[5];
    const float* mw      = (const float*)d_in[6];
    const float* mb      = (const float*)d_in[7];
    float* out = (float*)d_out;

    dim3 gwh(NTFLAT / 128, BB, SS);
    dim3 gfm(BB, SS);
    dim3 gagg(TT, BB, SS);
    dim3 gmlp(NN, BB);

    adjbit_kernel<<<BB * SS, 256>>>(support);

    wh_kernel<<<gwh, 256>>>(x, W1, a1, 0);
    f2max_kernel<<<gfm, 64>>>();
    agg_kernel<<<gagg, 448>>>(0);

    wh_kernel<<<gwh, 256>>>(x, WK, aK, 1);
    f2max_kernel<<<gfm, 64>>>();
    agg_kernel<<<gagg, 448>>>(1);

    mlp_kernel<<<gmlp, 192>>>(x, mw, mb, out);
}

// round 10
// speedup vs baseline: 1.1822x; 1.1719x over previous
#include <cuda_runtime.h>
#include <cuda_bf16.h>

#define BB 16
#define FF 32
#define CC 32
#define NN 200
#define TT 48
#define SS 3
#define MC 24               // m-chunk in agg (3 k-steps of 8)
#define NCH 9               // 8 full chunks + 1 partial (8)
#define NP 224              // padded N (14 x 16-row mma bands)
#define NTFLAT (NN * TT)    // 9600

// ---- tf32 helpers ----
__device__ __forceinline__ unsigned tf32r(float f) {
    unsigned u; asm("cvt.rna.tf32.f32 %0, %1;" : "=r"(u) : "f"(f)); return u;
}
__device__ __forceinline__ void mma_tf32(float* d,
    unsigned a0, unsigned a1, unsigned a2, unsigned a3,
    unsigned b0, unsigned b1)
{
    asm("mma.sync.aligned.m16n8k8.row.col.f32.tf32.tf32.f32 "
        "{%0,%1,%2,%3}, {%4,%5,%6,%7}, {%8,%9}, {%0,%1,%2,%3};"
        : "+f"(d[0]), "+f"(d[1]), "+f"(d[2]), "+f"(d[3])
        : "r"(a0), "r"(a1), "r"(a2), "r"(a3), "r"(b0), "r"(b1));
}

// ---- cp.async helpers ----
__device__ __forceinline__ unsigned smem_u32(const void* p) {
    return (unsigned)__cvta_generic_to_shared(p);
}
#define CPA16(d, s) asm volatile("cp.async.cg.shared.global [%0], [%1], 16;" :: "r"(d), "l"(s))
#define CPC()       asm volatile("cp.async.commit_group;")
#define CPW0()      asm volatile("cp.async.wait_group 0;" ::: "memory")

// Scratch (device globals)
__device__ float g_wh[SS][BB][NTFLAT * CC];       // tf32-rounded Wh, [(n,t)][c]
__device__ float g_f1t[SS][BB][TT * NP];          // [t][n]
__device__ float g_f2t[SS][BB][TT * NP];          // [t][n]
__device__ float g_f2max[SS][BB][TT];
__device__ unsigned g_adjb[BB * SS][NCH][NP];     // 24-bit masks per chunk
__device__ float g_y[6][BB][NTFLAT * CC];         // slot = 2*s + hop

// ---------------------------------------------------------------------------
// Adjacency bit-pack (24 bits per chunk word). grid 48, 256 threads.
// ---------------------------------------------------------------------------
__global__ void adjbit_kernel(const int* __restrict__ support)
{
    const int bs = blockIdx.x;
    const int warp = threadIdx.x >> 5, lane = threadIdx.x & 31;
    const int* adj = support + (size_t)bs * NN * NN;
    for (int pid = warp; pid < NN * NCH; pid += 8) {
        int n = pid / NCH, wi = pid % NCH;
        int mm = wi * MC + lane;
        int v = (lane < MC && mm < NN) ? (adj[n * NN + mm] > 0) : 0;
        unsigned word = __ballot_sync(0xffffffffu, v);
        if (lane == 0) g_adjb[bs][wi][n] = word;
    }
    if (threadIdx.x < NP - NN) {
        for (int wi = 0; wi < NCH; wi++) g_adjb[bs][wi][NN + threadIdx.x] = 0u;
    }
}

// ---------------------------------------------------------------------------
// Wh + f1/f2 (t-major f-outputs; Wh stored pre-rounded to tf32).
// grid (75, BB, SS), 256 threads.
// ---------------------------------------------------------------------------
__global__ __launch_bounds__(256) void wh_kernel(
    const float* __restrict__ xin,
    const float* __restrict__ Wb,
    const float* __restrict__ ab,
    int layout)
{
    const int b = blockIdx.y, s = blockIdx.z;
    const int base = blockIdx.x * 128;
    const int tid = threadIdx.x;

    __shared__ float xs[128 * 33];
    __shared__ float Ws[FF * CC];
    __shared__ float as_[2 * CC];

    if (layout == 0) {
        const float* src = xin + (size_t)b * FF * NTFLAT + base;
        #pragma unroll
        for (int k = 0; k < 4; k++) {
            int idx4 = tid + 256 * k;
            int f = idx4 >> 5, r4 = (idx4 & 31) * 4;
            float4 v = *(const float4*)(src + (size_t)f * NTFLAT + r4);
            xs[(r4 + 0) * 33 + f] = v.x;
            xs[(r4 + 1) * 33 + f] = v.y;
            xs[(r4 + 2) * 33 + f] = v.z;
            xs[(r4 + 3) * 33 + f] = v.w;
        }
    } else {
        const float* src = &g_y[2 * s][b][(size_t)base * CC];
        #pragma unroll
        for (int k = 0; k < 4; k++) {
            int idx4 = tid + 256 * k;
            int row = idx4 >> 3, q = (idx4 & 7) * 4;
            float4 v = *(const float4*)(src + idx4 * 4);
            xs[row * 33 + q + 0] = v.x;
            xs[row * 33 + q + 1] = v.y;
            xs[row * 33 + q + 2] = v.z;
            xs[row * 33 + q + 3] = v.w;
        }
    }
    {
        const float* W = Wb + (s * BB + b) * (FF * CC);
        if (tid < 256) ((float4*)Ws)[tid] = ((const float4*)W)[tid];
        if (tid < 2 * CC) as_[tid] = ab[(s * BB + b) * (2 * CC) + tid];
    }
    __syncthreads();

    const int cg = tid & 15, rg = tid >> 4;
    const int r0 = rg * 8;
    float acc[8][2];
    #pragma unroll
    for (int i = 0; i < 8; i++) { acc[i][0] = 0.f; acc[i][1] = 0.f; }

    #pragma unroll 8
    for (int f = 0; f < FF; f++) {
        float2 wv = *(const float2*)&Ws[f * CC + 2 * cg];
        #pragma unroll
        for (int i = 0; i < 8; i++) {
            float xv = xs[(r0 + i) * 33 + f];
            acc[i][0] += xv * wv.x;
            acc[i][1] += xv * wv.y;
        }
    }

    float* hp = &g_wh[s][b][0];
    #pragma unroll
    for (int i = 0; i < 8; i++) {
        unsigned h0 = tf32r(acc[i][0]);
        unsigned h1 = tf32r(acc[i][1]);
        size_t off = (size_t)(base + r0 + i) * CC + 2 * cg;
        *(float2*)&hp[off] = make_float2(__uint_as_float(h0), __uint_as_float(h1));
    }

    float a1l = as_[2 * cg], a1h = as_[2 * cg + 1];
    float a2l = as_[CC + 2 * cg], a2h = as_[CC + 2 * cg + 1];
    #pragma unroll
    for (int i = 0; i < 8; i++) {
        float p1 = acc[i][0] * a1l + acc[i][1] * a1h;
        float p2 = acc[i][0] * a2l + acc[i][1] * a2h;
        #pragma unroll
        for (int off = 8; off >= 1; off >>= 1) {
            p1 += __shfl_xor_sync(0xffffffffu, p1, off);
            p2 += __shfl_xor_sync(0xffffffffu, p2, off);
        }
        if (cg == 0) {
            int row = base + r0 + i;
            int n = row / TT, t = row % TT;
            g_f1t[s][b][t * NP + n] = p1;
            g_f2t[s][b][t * NP + n] = p2;
        }
    }
}

// ---------------------------------------------------------------------------
__global__ void f2max_kernel()
{
    const int b = blockIdx.x, s = blockIdx.y, t = threadIdx.x;
    if (t < TT) {
        const float* p = &g_f2t[s][b][t * NP];
        float m = -1e30f;
        for (int n = 0; n < NN; n++) m = fmaxf(m, p[n]);
        g_f2max[s][b][t] = m;
    }
}

// ---------------------------------------------------------------------------
// Attention-aggregation, 1x tf32 mma. grid (TT, BB, SS), block 448 (14 warps).
// Warp w owns n-rows [16w, 16w+16); 4 c-tiles of 8 per warp.
// ---------------------------------------------------------------------------
__global__ __launch_bounds__(448, 2) void agg_kernel(int hop)
{
    const int t = blockIdx.x, b = blockIdx.y, s = blockIdx.z;
    const int bs = b * SS + s;
    const int tid = threadIdx.x;
    const int lane = tid & 31, wid = tid >> 5;
    const int grp = lane >> 2, kq = lane & 3;

    __shared__ __align__(16) float whs[2][MC * 36];      // [m][c] stride 36
    __shared__ __align__(16) float wsm[NP * 28];         // [n][m] stride 28
    __shared__ __align__(16) float f2c[2][MC];
    __shared__ __align__(16) unsigned adjw[2][NP];
    __shared__ float zsm[NP];

    const float* whbase = &g_wh[s][b][0];
    const float* f1tp = &g_f1t[s][b][t * NP];
    const float* f2tp = &g_f2t[s][b][t * NP];
    const float fms = g_f2max[s][b][t];

    auto prefetch = [&](int k, int bf) {
        const int m0 = k * MC;
        if (tid < MC * 8) {                 // 192 threads
            int m = tid >> 3, q = tid & 7;
            int mrow = min(m0 + m, NN - 1);
            CPA16(smem_u32(&whs[bf][m * 36 + q * 4]),
                  whbase + ((size_t)mrow * TT + t) * CC + q * 4);
        }
        if (tid < MC / 4)
            CPA16(smem_u32(&f2c[bf][tid * 4]), f2tp + m0 + tid * 4);
        if (tid < NP / 4)
            CPA16(smem_u32(&adjw[bf][tid * 4]), &g_adjb[bs][k][tid * 4]);
        CPC();
    };

    prefetch(0, 0);

    // zero wsm pad rows [NN, NP) once
    for (int i = tid; i < (NP - NN) * 28; i += 448)
        wsm[(NN + i / 28) * 28 + (i % 28)] = 0.f;

    float f1v = 0.f, mhv = 0.f, z = 0.f;
    if (tid < NN) {
        f1v = f1tp[tid];
        float sv = f1v + fms;
        mhv = fmaxf(sv, 0.2f * sv);
    }

    float d[4][4];
    #pragma unroll
    for (int j = 0; j < 4; j++)
        #pragma unroll
        for (int q = 0; q < 4; q++) d[j][q] = 0.f;

    const int r0 = 16 * wid + grp;

    for (int k = 0; k < NCH; k++) {
        const int bf = k & 1;
        const int mc = (k == NCH - 1) ? (NN - (NCH - 1) * MC) : MC;   // 8 or 24
        CPW0();
        __syncthreads();
        if (k + 1 < NCH) prefetch(k + 1, bf ^ 1);

        // step 1: thread n computes weights -> wsm[n][m], accumulates Z
        if (tid < NN) {
            unsigned aw = adjw[bf][tid];
            #pragma unroll
            for (int q = 0; q < MC / 4; q++) {
                if (4 * q >= mc) break;
                float4 wq;
                float* wp = &wq.x;
                #pragma unroll
                for (int j = 0; j < 4; j++) {
                    int m = 4 * q + j;
                    float sv = f1v + f2c[bf][m];
                    float e = fmaxf(sv, 0.2f * sv);
                    float w = ((aw >> m) & 1u) ? __expf(e - mhv) : 0.f;
                    wp[j] = w;
                    z += w;
                }
                *(float4*)&wsm[tid * 28 + 4 * q] = wq;
            }
        }
        __syncthreads();

        // step 2: 1x tf32 mma over k-steps of 8
        const int nks = mc >> 3;
        for (int ks = 0; ks < nks; ks++) {
            unsigned a0 = tf32r(wsm[r0 * 28 + ks * 8 + kq]);
            unsigned a1 = tf32r(wsm[(r0 + 8) * 28 + ks * 8 + kq]);
            unsigned a2 = tf32r(wsm[r0 * 28 + ks * 8 + kq + 4]);
            unsigned a3 = tf32r(wsm[(r0 + 8) * 28 + ks * 8 + kq + 4]);
            #pragma unroll
            for (int j = 0; j < 4; j++) {
                int c0 = 8 * j + grp;
                int mr = ks * 8 + kq;
                unsigned bh0 = __float_as_uint(whs[bf][mr * 36 + c0]);
                unsigned bh1 = __float_as_uint(whs[bf][(mr + 4) * 36 + c0]);
                mma_tf32(d[j], a0, a1, a2, a3, bh0, bh1);
            }
        }
    }

    if (tid < NN) zsm[tid] = z;
    __syncthreads();

    const int slot = 2 * s + hop;
    float* yp = &g_y[slot][b][0];
    #pragma unroll
    for (int half = 0; half < 2; half++) {
        int n = r0 + 8 * half;
        if (n < NN) {
            float zv = fmaxf(zsm[n], 1e-30f);
            #pragma unroll
            for (int j = 0; j < 4; j++) {
                float h0 = __fdividef(d[j][2 * half], zv);
                float h1 = __fdividef(d[j][2 * half + 1], zv);
                float y0, y1;
                if (hop == 0) {
                    y0 = (h0 > 0.f) ? h0 : (__expf(h0) - 1.f);
                    y1 = (h1 > 0.f) ? h1 : (__expf(h1) - 1.f);
                } else {
                    y0 = fmaxf(h0, 0.f);
                    y1 = fmaxf(h1, 0.f);
                }
                *(float2*)&yp[(size_t)(n * TT + t) * CC + 8 * j + 2 * kq] =
                    make_float2(y0, y1);
            }
        }
    }
}

// ---------------------------------------------------------------------------
// Final concat + 1x1 conv, cp.async double-buffered. grid (NN, BB), block 192.
// ---------------------------------------------------------------------------
__global__ __launch_bounds__(192) void mlp_kernel(
    const float* __restrict__ x,
    const float* __restrict__ mw,
    const float* __restrict__ mb,
    float* __restrict__ out)
{
    const int n = blockIdx.x, b = blockIdx.y;
    const int tid = threadIdx.x;
    __shared__ __align__(16) float hb[2][TT * 32];
    __shared__ __align__(16) float wb[2][64 * 36];

    auto prefetch = [&](int blk, int bf) {
        const float* src = &g_y[blk - 1][b][(size_t)n * TT * CC];
        #pragma unroll
        for (int i = tid; i < 384; i += 192)
            CPA16(smem_u32(&hb[bf][i * 4]), src + i * 4);
        #pragma unroll
        for (int i = tid; i < 512; i += 192) {
            int o = i >> 3, q = i & 7;
            CPA16(smem_u32(&wb[bf][o * 36 + q * 4]), mw + o * 224 + blk * 32 + q * 4);
        }
        CPC();
    };

    // blk 0: synchronous transpose-load of x + wb chunk 0
    for (int idx = tid; idx < TT * 32; idx += 192) {
        int f = idx / TT, t = idx % TT;
        hb[0][t * 32 + f] = x[((size_t)(b * FF + f) * NN + n) * TT + t];
    }
    for (int idx = tid; idx < 64 * 32; idx += 192) {
        int o = idx / 32, c = idx % 32;
        wb[0][o * 36 + c] = mw[o * 224 + c];
    }
    prefetch(1, 1);
    __syncthreads();

    const int og = tid % 16, tg = tid / 16;
    float acc[4][4];
    #pragma unroll
    for (int i = 0; i < 4; i++)
        #pragma unroll
        for (int j = 0; j < 4; j++) acc[i][j] = 0.f;

    for (int blk = 0; blk < 7; blk++) {
        const int bf = blk & 1;
        #pragma unroll
        for (int cc = 0; cc < 32; cc += 4) {
            float4 hv[4], wv[4];
            #pragma unroll
            for (int j = 0; j < 4; j++) hv[j] = *(const float4*)&hb[bf][(tg * 4 + j) * 32 + cc];
            #pragma unroll
            for (int i = 0; i < 4; i++) wv[i] = *(const float4*)&wb[bf][(og + 16 * i) * 36 + cc];
            #pragma unroll
            for (int i = 0; i < 4; i++)
                #pragma unroll
                for (int j = 0; j < 4; j++)
                    acc[i][j] += wv[i].x * hv[j].x + wv[i].y * hv[j].y
                               + wv[i].z * hv[j].z + wv[i].w * hv[j].w;
        }
        if (blk + 1 < 7) {
            CPW0();
            __syncthreads();
            if (blk + 2 < 7) prefetch(blk + 2, bf);
        }
    }

    #pragma unroll
    for (int i = 0; i < 4; i++) {
        int o = og + 16 * i;
        float bias = mb[o];
        float4 r = make_float4(acc[i][0] + bias, acc[i][1] + bias,
                               acc[i][2] + bias, acc[i][3] + bias);
        *(float4*)&out[((size_t)(b * 64 + o) * NN + n) * TT + tg * 4] = r;
    }
}

// ---------------------------------------------------------------------------
extern "C" void kernel_launch(void* const* d_in, const int* in_sizes, int n_in,
                              void* d_out, int out_size)
{
    const float* x       = (const float*)d_in[0];
    const int*   support = (const int*)  d_in[1];
    const float* W1      = (const float*)d_in[2];
    const float* a1      = (const float*)d_in[3];
    const float* WK      = (const float*)d_in[4];
    const float* aK      = (const float*)d_in[5];
    const float* mw      = (const float*)d_in[6];
    const float* mb      = (const float*)d_in[7];
    float* out = (float*)d_out;

    dim3 gwh(NTFLAT / 128, BB, SS);
    dim3 gfm(BB, SS);
    dim3 gagg(TT, BB, SS);
    dim3 gmlp(NN, BB);

    adjbit_kernel<<<BB * SS, 256>>>(support);

    wh_kernel<<<gwh, 256>>>(x, W1, a1, 0);
    f2max_kernel<<<gfm, 64>>>();
    agg_kernel<<<gagg, 448>>>(0);

    wh_kernel<<<gwh, 256>>>(x, WK, aK, 1);
    f2max_kernel<<<gfm, 64>>>();
    agg_kernel<<<gagg, 448>>>(1);

    mlp_kernel<<<gmlp, 192>>>(x, mw, mb, out);
}

// round 12
// speedup vs baseline: 1.1981x; 1.0135x over previous
#include <cuda_runtime.h>
#include <cuda_bf16.h>

#define BB 16
#define FF 32
#define CC 32
#define NN 200
#define TT 48
#define SS 3
#define MC 16               // m-chunk in agg (2 k-steps of 8)
#define NCH 13              // 12 full chunks + 1 partial (8)
#define NP 224              // padded N (14 x 16-row mma bands)
#define WS 20               // wsm row stride (conflict-free: 20 % 8 == 4)
#define NTFLAT (NN * TT)    // 9600

// ---- tf32 helpers ----
__device__ __forceinline__ unsigned tf32r(float f) {
    unsigned u; asm("cvt.rna.tf32.f32 %0, %1;" : "=r"(u) : "f"(f)); return u;
}
__device__ __forceinline__ void mma_tf32(float* d,
    unsigned a0, unsigned a1, unsigned a2, unsigned a3,
    unsigned b0, unsigned b1)
{
    asm("mma.sync.aligned.m16n8k8.row.col.f32.tf32.tf32.f32 "
        "{%0,%1,%2,%3}, {%4,%5,%6,%7}, {%8,%9}, {%0,%1,%2,%3};"
        : "+f"(d[0]), "+f"(d[1]), "+f"(d[2]), "+f"(d[3])
        : "r"(a0), "r"(a1), "r"(a2), "r"(a3), "r"(b0), "r"(b1));
}

// ---- cp.async helpers ----
__device__ __forceinline__ unsigned smem_u32(const void* p) {
    return (unsigned)__cvta_generic_to_shared(p);
}
#define CPA16(d, s) asm volatile("cp.async.cg.shared.global [%0], [%1], 16;" :: "r"(d), "l"(s))
#define CPC()       asm volatile("cp.async.commit_group;")
#define CPW0()      asm volatile("cp.async.wait_group 0;" ::: "memory")

// Scratch (device globals)
__device__ float g_wh[SS][BB][NTFLAT * CC];       // tf32-rounded Wh, [(n,t)][c]
__device__ float g_f1t[SS][BB][TT * NP];          // [t][n]
__device__ float g_f2t[SS][BB][TT * NP];          // [t][n]
__device__ float g_f2max[SS][BB][TT];
__device__ unsigned g_adjb[BB * SS][NCH][NP];     // 16-bit masks per chunk
__device__ float g_y[6][BB][NTFLAT * CC];         // slot = 2*s + hop

// ---------------------------------------------------------------------------
// Adjacency bit-pack (16 bits per chunk word). grid 48, 256 threads.
// ---------------------------------------------------------------------------
__global__ void adjbit_kernel(const int* __restrict__ support)
{
    const int bs = blockIdx.x;
    const int warp = threadIdx.x >> 5, lane = threadIdx.x & 31;
    const int* adj = support + (size_t)bs * NN * NN;
    for (int pid = warp; pid < NN * NCH; pid += 8) {
        int n = pid / NCH, wi = pid % NCH;
        int mm = wi * MC + lane;
        int v = (lane < MC && mm < NN) ? (adj[n * NN + mm] > 0) : 0;
        unsigned word = __ballot_sync(0xffffffffu, v);
        if (lane == 0) g_adjb[bs][wi][n] = word;
    }
    if (threadIdx.x < NP - NN) {
        for (int wi = 0; wi < NCH; wi++) g_adjb[bs][wi][NN + threadIdx.x] = 0u;
    }
}

// ---------------------------------------------------------------------------
// Wh + f1/f2 (t-major f-outputs; Wh stored pre-rounded to tf32).
// grid (75, BB, SS), 256 threads.
// ---------------------------------------------------------------------------
__global__ __launch_bounds__(256) void wh_kernel(
    const float* __restrict__ xin,
    const float* __restrict__ Wb,
    const float* __restrict__ ab,
    int layout)
{
    const int b = blockIdx.y, s = blockIdx.z;
    const int base = blockIdx.x * 128;
    const int tid = threadIdx.x;

    __shared__ float xs[128 * 33];
    __shared__ float Ws[FF * CC];
    __shared__ float as_[2 * CC];

    if (layout == 0) {
        const float* src = xin + (size_t)b * FF * NTFLAT + base;
        #pragma unroll
        for (int k = 0; k < 4; k++) {
            int idx4 = tid + 256 * k;
            int f = idx4 >> 5, r4 = (idx4 & 31) * 4;
            float4 v = *(const float4*)(src + (size_t)f * NTFLAT + r4);
            xs[(r4 + 0) * 33 + f] = v.x;
            xs[(r4 + 1) * 33 + f] = v.y;
            xs[(r4 + 2) * 33 + f] = v.z;
            xs[(r4 + 3) * 33 + f] = v.w;
        }
    } else {
        const float* src = &g_y[2 * s][b][(size_t)base * CC];
        #pragma unroll
        for (int k = 0; k < 4; k++) {
            int idx4 = tid + 256 * k;
            int row = idx4 >> 3, q = (idx4 & 7) * 4;
            float4 v = *(const float4*)(src + idx4 * 4);
            xs[row * 33 + q + 0] = v.x;
            xs[row * 33 + q + 1] = v.y;
            xs[row * 33 + q + 2] = v.z;
            xs[row * 33 + q + 3] = v.w;
        }
    }
    {
        const float* W = Wb + (s * BB + b) * (FF * CC);
        if (tid < 256) ((float4*)Ws)[tid] = ((const float4*)W)[tid];
        if (tid < 2 * CC) as_[tid] = ab[(s * BB + b) * (2 * CC) + tid];
    }
    __syncthreads();

    const int cg = tid & 15, rg = tid >> 4;
    const int r0 = rg * 8;
    float acc[8][2];
    #pragma unroll
    for (int i = 0; i < 8; i++) { acc[i][0] = 0.f; acc[i][1] = 0.f; }

    #pragma unroll 8
    for (int f = 0; f < FF; f++) {
        float2 wv = *(const float2*)&Ws[f * CC + 2 * cg];
        #pragma unroll
        for (int i = 0; i < 8; i++) {
            float xv = xs[(r0 + i) * 33 + f];
            acc[i][0] += xv * wv.x;
            acc[i][1] += xv * wv.y;
        }
    }

    float* hp = &g_wh[s][b][0];
    #pragma unroll
    for (int i = 0; i < 8; i++) {
        unsigned h0 = tf32r(acc[i][0]);
        unsigned h1 = tf32r(acc[i][1]);
        size_t off = (size_t)(base + r0 + i) * CC + 2 * cg;
        *(float2*)&hp[off] = make_float2(__uint_as_float(h0), __uint_as_float(h1));
    }

    float a1l = as_[2 * cg], a1h = as_[2 * cg + 1];
    float a2l = as_[CC + 2 * cg], a2h = as_[CC + 2 * cg + 1];
    #pragma unroll
    for (int i = 0; i < 8; i++) {
        float p1 = acc[i][0] * a1l + acc[i][1] * a1h;
        float p2 = acc[i][0] * a2l + acc[i][1] * a2h;
        #pragma unroll
        for (int off = 8; off >= 1; off >>= 1) {
            p1 += __shfl_xor_sync(0xffffffffu, p1, off);
            p2 += __shfl_xor_sync(0xffffffffu, p2, off);
        }
        if (cg == 0) {
            int row = base + r0 + i;
            int n = row / TT, t = row % TT;
            g_f1t[s][b][t * NP + n] = p1;
            g_f2t[s][b][t * NP + n] = p2;
        }
    }
}

// ---------------------------------------------------------------------------
__global__ void f2max_kernel()
{
    const int b = blockIdx.x, s = blockIdx.y, t = threadIdx.x;
    if (t < TT) {
        const float* p = &g_f2t[s][b][t * NP];
        float m = -1e30f;
        for (int n = 0; n < NN; n++) m = fmaxf(m, p[n]);
        g_f2max[s][b][t] = m;
    }
}

// ---------------------------------------------------------------------------
// Attention-aggregation, 1x tf32 mma, fused single-barrier pipeline.
// grid (TT, BB, SS), block 448 (14 warps). Warp w owns n-rows [16w, 16w+16).
// Iteration k: prefetch(k+1,k+2) -> step1(k+1) -> step2(k) -> barrier.
// ---------------------------------------------------------------------------
__global__ __launch_bounds__(448, 2) void agg_kernel(int hop)
{
    const int t = blockIdx.x, b = blockIdx.y, s = blockIdx.z;
    const int bs = b * SS + s;
    const int tid = threadIdx.x;
    const int lane = tid & 31, wid = tid >> 5;
    const int grp = lane >> 2, kq = lane & 3;

    __shared__ __align__(16) float whs[2][MC * 36];      // [m][c] stride 36
    __shared__ __align__(16) float wsm[2][NP * WS];      // [n][m] stride 20
    __shared__ __align__(16) float f2c[2][MC];
    __shared__ __align__(16) unsigned adjw[2][NP];
    __shared__ float zsm[NP];

    const float* whbase = &g_wh[s][b][0];
    const float* f1tp = &g_f1t[s][b][t * NP];
    const float* f2tp = &g_f2t[s][b][t * NP];
    const float fms = g_f2max[s][b][t];

    auto prefetch_whs = [&](int k) {
        const int bf = k & 1;
        if (tid < MC * 8) {                 // 128 threads
            int m = tid >> 3, q = tid & 7;
            int mrow = min(k * MC + m, NN - 1);
            CPA16(smem_u32(&whs[bf][m * 36 + q * 4]),
                  whbase + ((size_t)mrow * TT + t) * CC + q * 4);
        }
    };
    auto prefetch_small = [&](int k) {
        const int bf = k & 1;
        if (tid < MC / 4)
            CPA16(smem_u32(&f2c[bf][tid * 4]), f2tp + k * MC + tid * 4);
        if (tid < NP / 4)
            CPA16(smem_u32(&adjw[bf][tid * 4]), &g_adjb[bs][k][tid * 4]);
    };

    // step1 for chunk kk (threads < NN): weights -> wsm[kk&1], z accumulation
    float f1v = 0.f, mhv = 0.f, z = 0.f;

    auto step1 = [&](int kk) {
        if (tid < NN) {
            const int bf = kk & 1;
            unsigned aw = adjw[bf][tid];
            const int mcn = (kk == NCH - 1) ? (NN - (NCH - 1) * MC) : MC;
            #pragma unroll
            for (int q = 0; q < MC / 4; q++) {
                if (4 * q >= mcn) break;
                float4 wq;
                float* wp = &wq.x;
                #pragma unroll
                for (int j = 0; j < 4; j++) {
                    int m = 4 * q + j;
                    float sv = f1v + f2c[bf][m];
                    float e = fmaxf(sv, 0.2f * sv);
                    float w = ((aw >> m) & 1u) ? __expf(e - mhv) : 0.f;
                    wp[j] = w;
                    z += w;
                }
                *(float4*)&wsm[bf][tid * WS + 4 * q] = wq;
            }
        }
    };

    // ---- prologue: G_{-1} = {whs(0), small(0), small(1)} ----
    prefetch_whs(0);
    prefetch_small(0);
    prefetch_small(1);
    CPC();

    // zero wsm pad rows [NN, NP) in both buffers
    for (int i = tid; i < (NP - NN) * WS; i += 448) {
        int n = NN + i / WS, m = i % WS;
        wsm[0][n * WS + m] = 0.f;
        wsm[1][n * WS + m] = 0.f;
    }
    if (tid < NN) {
        f1v = f1tp[tid];
        float sv = f1v + fms;
        mhv = fmaxf(sv, 0.2f * sv);
    }

    CPW0();
    __syncthreads();
    step1(0);
    __syncthreads();          // publish wsm(0); whs(0)/small already synced

    float d[4][4];
    #pragma unroll
    for (int j = 0; j < 4; j++)
        #pragma unroll
        for (int q = 0; q < 4; q++) d[j][q] = 0.f;

    const int r0 = 16 * wid + grp;

    for (int k = 0; k < NCH; k++) {
        const int bf = k & 1;
        // issue next prefetches (buffers freed by the barrier that ended iter k-1)
        if (k + 1 < NCH) prefetch_whs(k + 1);
        if (k + 2 < NCH) prefetch_small(k + 2);
        CPC();

        // step1 for k+1 (reads small(k+1): landed + synced)
        if (k + 1 < NCH) step1(k + 1);

        // step2 for k: tf32 mma from wsm[bf], whs[bf]
        const int mc = (k == NCH - 1) ? (NN - (NCH - 1) * MC) : MC;
        const int nks = mc >> 3;
        for (int ks = 0; ks < nks; ks++) {
            unsigned a0 = tf32r(wsm[bf][r0 * WS + ks * 8 + kq]);
            unsigned a1 = tf32r(wsm[bf][(r0 + 8) * WS + ks * 8 + kq]);
            unsigned a2 = tf32r(wsm[bf][r0 * WS + ks * 8 + kq + 4]);
            unsigned a3 = tf32r(wsm[bf][(r0 + 8) * WS + ks * 8 + kq + 4]);
            #pragma unroll
            for (int j = 0; j < 4; j++) {
                int c0 = 8 * j + grp;
                int mr = ks * 8 + kq;
                unsigned bh0 = __float_as_uint(whs[bf][mr * 36 + c0]);
                unsigned bh1 = __float_as_uint(whs[bf][(mr + 4) * 36 + c0]);
                mma_tf32(d[j], a0, a1, a2, a3, bh0, bh1);
            }
        }

        // single barrier: publishes wsm(k+1), frees whs[bf]/wsm[bf] for reuse,
        // and (with the per-thread CPW0 below) orders cp.async data.
        CPW0();
        __syncthreads();
    }

    if (tid < NN) zsm[tid] = z;
    __syncthreads();

    const int slot = 2 * s + hop;
    float* yp = &g_y[slot][b][0];
    #pragma unroll
    for (int half = 0; half < 2; half++) {
        int n = r0 + 8 * half;
        if (n < NN) {
            float zv = fmaxf(zsm[n], 1e-30f);
            #pragma unroll
            for (int j = 0; j < 4; j++) {
                float h0 = __fdividef(d[j][2 * half], zv);
                float h1 = __fdividef(d[j][2 * half + 1], zv);
                float y0, y1;
                if (hop == 0) {
                    y0 = (h0 > 0.f) ? h0 : (__expf(h0) - 1.f);
                    y1 = (h1 > 0.f) ? h1 : (__expf(h1) - 1.f);
                } else {
                    y0 = fmaxf(h0, 0.f);
                    y1 = fmaxf(h1, 0.f);
                }
                *(float2*)&yp[(size_t)(n * TT + t) * CC + 8 * j + 2 * kq] =
                    make_float2(y0, y1);
            }
        }
    }
}

// ---------------------------------------------------------------------------
// Final concat + 1x1 conv, cp.async double-buffered. grid (NN, BB), block 192.
// ---------------------------------------------------------------------------
__global__ __launch_bounds__(192) void mlp_kernel(
    const float* __restrict__ x,
    const float* __restrict__ mw,
    const float* __restrict__ mb,
    float* __restrict__ out)
{
    const int n = blockIdx.x, b = blockIdx.y;
    const int tid = threadIdx.x;
    __shared__ __align__(16) float hb[2][TT * 32];
    __shared__ __align__(16) float wb[2][64 * 36];

    auto prefetch = [&](int blk, int bf) {
        const float* src = &g_y[blk - 1][b][(size_t)n * TT * CC];
        #pragma unroll
        for (int i = tid; i < 384; i += 192)
            CPA16(smem_u32(&hb[bf][i * 4]), src + i * 4);
        #pragma unroll
        for (int i = tid; i < 512; i += 192) {
            int o = i >> 3, q = i & 7;
            CPA16(smem_u32(&wb[bf][o * 36 + q * 4]), mw + o * 224 + blk * 32 + q * 4);
        }
        CPC();
    };

    for (int idx = tid; idx < TT * 32; idx += 192) {
        int f = idx / TT, t = idx % TT;
        hb[0][t * 32 + f] = x[((size_t)(b * FF + f) * NN + n) * TT + t];
    }
    for (int idx = tid; idx < 64 * 32; idx += 192) {
        int o = idx / 32, c = idx % 32;
        wb[0][o * 36 + c] = mw[o * 224 + c];
    }
    prefetch(1, 1);
    __syncthreads();

    const int og = tid % 16, tg = tid / 16;
    float acc[4][4];
    #pragma unroll
    for (int i = 0; i < 4; i++)
        #pragma unroll
        for (int j = 0; j < 4; j++) acc[i][j] = 0.f;

    for (int blk = 0; blk < 7; blk++) {
        const int bf = blk & 1;
        #pragma unroll
        for (int cc = 0; cc < 32; cc += 4) {
            float4 hv[4], wv[4];
            #pragma unroll
            for (int j = 0; j < 4; j++) hv[j] = *(const float4*)&hb[bf][(tg * 4 + j) * 32 + cc];
            #pragma unroll
            for (int i = 0; i < 4; i++) wv[i] = *(const float4*)&wb[bf][(og + 16 * i) * 36 + cc];
            #pragma unroll
            for (int i = 0; i < 4; i++)
                #pragma unroll
                for (int j = 0; j < 4; j++)
                    acc[i][j] += wv[i].x * hv[j].x + wv[i].y * hv[j].y
                               + wv[i].z * hv[j].z + wv[i].w * hv[j].w;
        }
        if (blk + 1 < 7) {
            CPW0();
            __syncthreads();
            if (blk + 2 < 7) prefetch(blk + 2, bf);
        }
    }

    #pragma unroll
    for (int i = 0; i < 4; i++) {
        int o = og + 16 * i;
        float bias = mb[o];
        float4 r = make_float4(acc[i][0] + bias, acc[i][1] + bias,
                               acc[i][2] + bias, acc[i][3] + bias);
        *(float4*)&out[((size_t)(b * 64 + o) * NN + n) * TT + tg * 4] = r;
    }
}

// ---------------------------------------------------------------------------
extern "C" void kernel_launch(void* const* d_in, const int* in_sizes, int n_in,
                              void* d_out, int out_size)
{
    const float* x       = (const float*)d_in[0];
    const int*   support = (const int*)  d_in[1];
    const float* W1      = (const float*)d_in[2];
    const float* a1      = (const float*)d_in[3];
    const float* WK      = (const float*)d_in[4];
    const float* aK      = (const float*)d_in[5];
    const float* mw      = (const float*)d_in[6];
    const float* mb      = (const float*)d_in[7];
    float* out = (float*)d_out;

    dim3 gwh(NTFLAT / 128, BB, SS);
    dim3 gfm(BB, SS);
    dim3 gagg(TT, BB, SS);
    dim3 gmlp(NN, BB);

    adjbit_kernel<<<BB * SS, 256>>>(support);

    wh_kernel<<<gwh, 256>>>(x, W1, a1, 0);
    f2max_kernel<<<gfm, 64>>>();
    agg_kernel<<<gagg, 448>>>(0);

    wh_kernel<<<gwh, 256>>>(x, WK, aK, 1);
    f2max_kernel<<<gfm, 64>>>();
    agg_kernel<<<gagg, 448>>>(1);

    mlp_kernel<<<gmlp, 192>>>(x, mw, mb, out);
}